// round 4
// baseline (speedup 1.0000x reference)
#include <cuda_runtime.h>
#include <cuda_fp16.h>

// VecInt: 7-step scaling-and-squaring integration of [2,128,128,128,3] f32.
//   v0 = vel/128;  v <- v + trilinear_warp(v, v)  x7
//
// R4: fp16x4 storage (R2) + dual-copy aligned-pair gathers.
// Each volume is kept twice: P (voxel v at slot v) and Q (voxel v at slot
// v+1). The two w-corners (iw0, iw0+1) of every trilinear row are then one
// 16B-aligned LDG.128 regardless of iw0 parity (pick P for even, Q for odd).
// This halves gather load count (8 -> 4) and cuts L1 wavefronts (the measured
// bottleneck: L1=77.8%, issue=66.5% in R2). All math in f32; rel_err
// identical to R2.

static constexpr int DIMS = 128;
static constexpr int NB   = 2;
static constexpr int NVOX = NB * DIMS * DIMS * DIMS;

// Two ping-pong volumes, each stored as P + Q (shifted) copies. +2 pad slots.
__device__ uint2 g_AP[NVOX + 2];
__device__ uint2 g_AQ[NVOX + 2];
__device__ uint2 g_BP[NVOX + 2];
__device__ uint2 g_BQ[NVOX + 2];

__device__ __forceinline__ void h4_to_f3(uint2 u, float& x, float& y, float& z)
{
    __half2 h01 = *reinterpret_cast<__half2*>(&u.x);
    __half2 h23 = *reinterpret_cast<__half2*>(&u.y);
    float2  f01 = __half22float2(h01);
    x = f01.x; y = f01.y; z = __low2float(h23);
}

__device__ __forceinline__ uint2 f3_to_h4(float x, float y, float z)
{
    __half2 h01 = __floats2half2_rn(x, y);
    __half2 h23 = __floats2half2_rn(z, 0.0f);
    uint2 u;
    u.x = *reinterpret_cast<unsigned int*>(&h01);
    u.y = *reinterpret_cast<unsigned int*>(&h23);
    return u;
}

// Unpack a voxel pair (uint4 = two fp16x4 voxels) to two f32x3.
__device__ __forceinline__ void pair_to_f3x2(uint4 u,
                                             float& x0, float& y0, float& z0,
                                             float& x1, float& y1, float& z1)
{
    __half2 a01 = *reinterpret_cast<__half2*>(&u.x);
    __half2 a2  = *reinterpret_cast<__half2*>(&u.y);
    __half2 b01 = *reinterpret_cast<__half2*>(&u.z);
    __half2 b2  = *reinterpret_cast<__half2*>(&u.w);
    float2 fa = __half22float2(a01);
    float2 fb = __half22float2(b01);
    x0 = fa.x; y0 = fa.y; z0 = __low2float(a2);
    x1 = fb.x; y1 = fb.y; z1 = __low2float(b2);
}

// ---------- pass 0: packed f32x3 -> fp16x4 into P and Q, folding 1/128 -----
__global__ __launch_bounds__(256)
void vecint_convert(const float4* __restrict__ in,
                    uint2* __restrict__ P, uint2* __restrict__ Q)
{
    const int t = blockIdx.x * blockDim.x + threadIdx.x;   // voxel-quad id
    const float s = 1.0f / 128.0f;
    const float4 a = in[3 * t + 0];
    const float4 b = in[3 * t + 1];
    const float4 c = in[3 * t + 2];
    uint2 v0 = f3_to_h4(a.x * s, a.y * s, a.z * s);
    uint2 v1 = f3_to_h4(a.w * s, b.x * s, b.y * s);
    uint2 v2 = f3_to_h4(b.z * s, b.w * s, c.x * s);
    uint2 v3 = f3_to_h4(c.y * s, c.z * s, c.w * s);
    const int i = 4 * t;
    P[i + 0] = v0; P[i + 1] = v1; P[i + 2] = v2; P[i + 3] = v3;
    Q[i + 1] = v0; Q[i + 2] = v1; Q[i + 3] = v2; Q[i + 4] = v3;
}

// ---------- integration step ------------------------------------------------
template<bool OUT_PACKED>
__global__ __launch_bounds__(256)
void vecint_step(const uint2* __restrict__ inP,   // natural copy
                 const uint2* __restrict__ inQ,   // shifted copy (slot v+1)
                 float*       __restrict__ out_p, // packed f32 (last pass)
                 uint2*       __restrict__ outP,
                 uint2*       __restrict__ outQ)
{
    const int w  = blockIdx.x * 32 + threadIdx.x;
    const int h  = blockIdx.y * 4  + threadIdx.y;
    const int zb = blockIdx.z;
    const int b  = zb >> 6;
    const int d  = ((zb & 63) << 1) + threadIdx.z;

    const int base = ((b * DIMS + d) * DIMS + h) * DIMS + w;

    float f0, f1, f2;
    h4_to_f3(inP[base], f0, f1, f2);

    const float ld = fminf(fmaxf((float)d + f0, 0.0f), 127.0f);
    const float lh = fminf(fmaxf((float)h + f1, 0.0f), 127.0f);
    const float lw = fminf(fmaxf((float)w + f2, 0.0f), 127.0f);

    const float fd = floorf(ld), fh = floorf(lh), fw = floorf(lw);
    const int   id0 = (int)fd,  ih0 = (int)fh,  iw0 = (int)fw;
    const float wd1 = ld - fd,  wh1 = lh - fh,  ww1 = lw - fw;
    const float wd0 = 1.0f - wd1, wh0 = 1.0f - wh1, ww0 = 1.0f - ww1;
    const int   id1 = min(id0 + 1, 127);
    const int   ih1 = min(ih0 + 1, 127);

    // Pair base: voxel idx lives at gb[idx], gb[idx] 16B-aligned for this
    // thread's parity. (Row strides are even, so parity(idx) == parity(iw0).)
    // Even iw0: P natural. Odd iw0: Q+1 (slot v+1 -> element v), (idx+1) even.
    const uint2* gb = (iw0 & 1) ? (inQ + 1) : inP;

    const int bb = b * DIMS * DIMS * DIMS;
    const int r00 = bb + (id0 * DIMS + ih0) * DIMS + iw0;
    const int r01 = bb + (id0 * DIMS + ih1) * DIMS + iw0;
    const int r10 = bb + (id1 * DIMS + ih0) * DIMS + iw0;
    const int r11 = bb + (id1 * DIMS + ih1) * DIMS + iw0;

    float r0 = 0.0f, r1 = 0.0f, r2 = 0.0f;
#pragma unroll
    for (int k = 0; k < 4; ++k) {
        const int   row = (k == 0) ? r00 : (k == 1) ? r01 : (k == 2) ? r10 : r11;
        const float wdh = ((k & 2) ? wd1 : wd0) * ((k & 1) ? wh1 : wh0);
        const float wg0 = wdh * ww0;
        const float wg1 = wdh * ww1;   // ww1==0 whenever the pair would stray
        const uint4 u = *reinterpret_cast<const uint4*>(gb + row);  // LDG.128
        float x0, y0, z0, x1, y1, z1;
        pair_to_f3x2(u, x0, y0, z0, x1, y1, z1);
        r0 = fmaf(wg0, x0, fmaf(wg1, x1, r0));
        r1 = fmaf(wg0, y0, fmaf(wg1, y1, r1));
        r2 = fmaf(wg0, z0, fmaf(wg1, z1, r2));
    }

    const float o0 = f0 + r0, o1 = f1 + r1, o2 = f2 + r2;
    if (OUT_PACKED) {
        float* p = out_p + (size_t)base * 3;
        p[0] = o0; p[1] = o1; p[2] = o2;
    } else {
        const uint2 v = f3_to_h4(o0, o1, o2);
        outP[base]     = v;
        outQ[base + 1] = v;
    }
}

extern "C" void kernel_launch(void* const* d_in, const int* in_sizes, int n_in,
                              void* d_out, int out_size)
{
    (void)in_sizes; (void)n_in; (void)out_size;
    const float4* vel = (const float4*)d_in[0];
    float*        out = (float*)d_out;

    uint2 *AP = nullptr, *AQ = nullptr, *BP = nullptr, *BQ = nullptr;
    cudaGetSymbolAddress((void**)&AP, g_AP);
    cudaGetSymbolAddress((void**)&AQ, g_AQ);
    cudaGetSymbolAddress((void**)&BP, g_BP);
    cudaGetSymbolAddress((void**)&BQ, g_BQ);

    vecint_convert<<<NVOX / 4 / 256, 256>>>(vel, AP, AQ);

    const dim3 blk(32, 4, 2);
    const dim3 grd(DIMS / 32, DIMS / 4, (DIMS / 2) * NB);

    vecint_step<false><<<grd, blk>>>(AP, AQ, nullptr, BP, BQ);   // 1
    vecint_step<false><<<grd, blk>>>(BP, BQ, nullptr, AP, AQ);   // 2
    vecint_step<false><<<grd, blk>>>(AP, AQ, nullptr, BP, BQ);   // 3
    vecint_step<false><<<grd, blk>>>(BP, BQ, nullptr, AP, AQ);   // 4
    vecint_step<false><<<grd, blk>>>(AP, AQ, nullptr, BP, BQ);   // 5
    vecint_step<false><<<grd, blk>>>(BP, BQ, nullptr, AP, AQ);   // 6
    vecint_step<true ><<<grd, blk>>>(AP, AQ, out, nullptr, nullptr); // 7
}

// round 5
// speedup vs baseline: 1.0774x; 1.0774x over previous
#include <cuda_runtime.h>
#include <cuda_fp16.h>

// VecInt: 7-step scaling-and-squaring integration of [2,128,128,128,3] f32.
//   v0 = vel/128;  v <- v + trilinear_warp(v, v)  x7
//
// R5: fp16x4 storage. Buffer A keeps a dual copy (P natural, Q shifted one
// slot) so the two w-corners of every trilinear row are one 16B-aligned
// LDG.128; buffer B keeps only P (R2-style 8x LDG.64 gather). Live set
// A(P+Q)+B(P) = 100.6MB fits the 126MB L2 (R4's 134MB thrashed it).
// Passes 1,3,5,7 read A (fast pair gather); 2,4,6 read B (plain gather) and
// rebuild A's dual copy on store. All math f32; rel_err identical to R2.

static constexpr int DIMS = 128;
static constexpr int NB   = 2;
static constexpr int NVOX = NB * DIMS * DIMS * DIMS;

__device__ __align__(16) uint2 g_AP[NVOX + 2];
__device__ __align__(16) uint2 g_AQ[NVOX + 2];
__device__ __align__(16) uint2 g_BP[NVOX + 2];

__device__ __forceinline__ void h4_to_f3(uint2 u, float& x, float& y, float& z)
{
    __half2 h01 = *reinterpret_cast<__half2*>(&u.x);
    __half2 h23 = *reinterpret_cast<__half2*>(&u.y);
    float2  f01 = __half22float2(h01);
    x = f01.x; y = f01.y; z = __low2float(h23);
}

__device__ __forceinline__ uint2 f3_to_h4(float x, float y, float z)
{
    __half2 h01 = __floats2half2_rn(x, y);
    __half2 h23 = __floats2half2_rn(z, 0.0f);
    uint2 u;
    u.x = *reinterpret_cast<unsigned int*>(&h01);
    u.y = *reinterpret_cast<unsigned int*>(&h23);
    return u;
}

__device__ __forceinline__ void pair_to_f3x2(uint4 u,
                                             float& x0, float& y0, float& z0,
                                             float& x1, float& y1, float& z1)
{
    __half2 a01 = *reinterpret_cast<__half2*>(&u.x);
    __half2 a2  = *reinterpret_cast<__half2*>(&u.y);
    __half2 b01 = *reinterpret_cast<__half2*>(&u.z);
    __half2 b2  = *reinterpret_cast<__half2*>(&u.w);
    float2 fa = __half22float2(a01);
    float2 fb = __half22float2(b01);
    x0 = fa.x; y0 = fa.y; z0 = __low2float(a2);
    x1 = fb.x; y1 = fb.y; z1 = __low2float(b2);
}

// ---------- pass 0: packed f32x3 -> fp16x4 into AP and AQ, folding 1/128 ----
__global__ __launch_bounds__(256)
void vecint_convert(const float4* __restrict__ in,
                    uint2* __restrict__ P, uint2* __restrict__ Q)
{
    const int t = blockIdx.x * blockDim.x + threadIdx.x;
    const float s = 1.0f / 128.0f;
    const float4 a = in[3 * t + 0];
    const float4 b = in[3 * t + 1];
    const float4 c = in[3 * t + 2];
    uint2 v0 = f3_to_h4(a.x * s, a.y * s, a.z * s);
    uint2 v1 = f3_to_h4(a.w * s, b.x * s, b.y * s);
    uint2 v2 = f3_to_h4(b.z * s, b.w * s, c.x * s);
    uint2 v3 = f3_to_h4(c.y * s, c.z * s, c.w * s);
    const int i = 4 * t;
    P[i + 0] = v0; P[i + 1] = v1; P[i + 2] = v2; P[i + 3] = v3;
    Q[i + 1] = v0; Q[i + 2] = v1; Q[i + 3] = v2; Q[i + 4] = v3;
}

// ---------- common coordinate setup ----------------------------------------
struct Coords {
    int   base, r00, r01, r10, r11, iw0;
    float f0, f1, f2, wd0, wd1, wh0, wh1, ww0, ww1;
};

__device__ __forceinline__ Coords setup(float f0, float f1, float f2,
                                        int b, int d, int h, int w)
{
    Coords c;
    c.f0 = f0; c.f1 = f1; c.f2 = f2;
    const float ld = fminf(fmaxf((float)d + f0, 0.0f), 127.0f);
    const float lh = fminf(fmaxf((float)h + f1, 0.0f), 127.0f);
    const float lw = fminf(fmaxf((float)w + f2, 0.0f), 127.0f);
    const float fd = floorf(ld), fh = floorf(lh), fw = floorf(lw);
    const int id0 = (int)fd, ih0 = (int)fh;
    c.iw0 = (int)fw;
    c.wd1 = ld - fd; c.wd0 = 1.0f - c.wd1;
    c.wh1 = lh - fh; c.wh0 = 1.0f - c.wh1;
    c.ww1 = lw - fw; c.ww0 = 1.0f - c.ww1;
    const int dd = (min(id0 + 1, 127) - id0) << 14;   // 0 or 16384
    const int dh = (min(ih0 + 1, 127) - ih0) << 7;    // 0 or 128
    c.r00 = ((b << 7) + id0 << 7) + ih0;
    c.r00 = (c.r00 << 7) + c.iw0;                     // bb + (id0*128+ih0)*128+iw0
    c.r01 = c.r00 + dh;
    c.r10 = c.r00 + dd;
    c.r11 = c.r10 + dh;
    c.base = ((b * DIMS + d) * DIMS + h) * DIMS + w;
    return c;
}

// ---------- fast step: pair gather from (P,Q) -------------------------------
template<bool OUT_PACKED>
__global__ __launch_bounds__(256)
void vecint_step_pair(const uint2* __restrict__ inP,
                      const uint2* __restrict__ inQ,
                      float*       __restrict__ out_p,
                      uint2*       __restrict__ outP)
{
    const int w  = blockIdx.x * 32 + threadIdx.x;
    const int h  = blockIdx.y * 4  + threadIdx.y;
    const int zb = blockIdx.z;
    const int b  = zb >> 6;
    const int d  = ((zb & 63) << 1) + threadIdx.z;

    const int base0 = ((b * DIMS + d) * DIMS + h) * DIMS + w;
    float f0, f1, f2;
    h4_to_f3(inP[base0], f0, f1, f2);

    const Coords c = setup(f0, f1, f2, b, d, h, w);

    // parity(idx) == parity(iw0); pick the copy whose pair is 16B-aligned.
    const uint2* gb = (c.iw0 & 1) ? (inQ + 1) : inP;

    float r0 = 0.0f, r1 = 0.0f, r2 = 0.0f;
#pragma unroll
    for (int k = 0; k < 4; ++k) {
        const int row = (k == 0) ? c.r00 : (k == 1) ? c.r01
                      : (k == 2) ? c.r10 : c.r11;
        const float wdh = ((k & 2) ? c.wd1 : c.wd0) * ((k & 1) ? c.wh1 : c.wh0);
        const float wg0 = wdh * c.ww0;
        const float wg1 = wdh * c.ww1;          // 0 whenever pair strays
        const uint4 u = *reinterpret_cast<const uint4*>(gb + row);  // LDG.128
        float x0, y0, z0, x1, y1, z1;
        pair_to_f3x2(u, x0, y0, z0, x1, y1, z1);
        r0 = fmaf(wg0, x0, fmaf(wg1, x1, r0));
        r1 = fmaf(wg0, y0, fmaf(wg1, y1, r1));
        r2 = fmaf(wg0, z0, fmaf(wg1, z1, r2));
    }

    const float o0 = f0 + r0, o1 = f1 + r1, o2 = f2 + r2;
    if (OUT_PACKED) {
        float* p = out_p + (size_t)base0 * 3;
        p[0] = o0; p[1] = o1; p[2] = o2;
    } else {
        outP[base0] = f3_to_h4(o0, o1, o2);
    }
}

// ---------- plain step: 8x LDG.64 from P, dual store to (P,Q) ---------------
__global__ __launch_bounds__(256)
void vecint_step_plain(const uint2* __restrict__ inP,
                       uint2* __restrict__ outP,
                       uint2* __restrict__ outQ)
{
    const int w  = blockIdx.x * 32 + threadIdx.x;
    const int h  = blockIdx.y * 4  + threadIdx.y;
    const int zb = blockIdx.z;
    const int b  = zb >> 6;
    const int d  = ((zb & 63) << 1) + threadIdx.z;

    const int base0 = ((b * DIMS + d) * DIMS + h) * DIMS + w;
    float f0, f1, f2;
    h4_to_f3(inP[base0], f0, f1, f2);

    const Coords c = setup(f0, f1, f2, b, d, h, w);

    float r0 = 0.0f, r1 = 0.0f, r2 = 0.0f;
#pragma unroll
    for (int k = 0; k < 4; ++k) {
        const int row = (k == 0) ? c.r00 : (k == 1) ? c.r01
                      : (k == 2) ? c.r10 : c.r11;
        const float wdh = ((k & 2) ? c.wd1 : c.wd0) * ((k & 1) ? c.wh1 : c.wh0);
        const float wg0 = wdh * c.ww0;
        const float wg1 = wdh * c.ww1;
        float x0, y0, z0, x1, y1, z1;
        h4_to_f3(inP[row], x0, y0, z0);
        // iw0==127 -> ww1==0, read the same voxel (harmless, weight 0) to
        // avoid straying; min() keeps index in-bounds cheaply via pad anyway.
        h4_to_f3(inP[row + 1], x1, y1, z1);
        r0 = fmaf(wg0, x0, fmaf(wg1, x1, r0));
        r1 = fmaf(wg0, y0, fmaf(wg1, y1, r1));
        r2 = fmaf(wg0, z0, fmaf(wg1, z1, r2));
    }

    const uint2 v = f3_to_h4(f0 + r0, f1 + r1, f2 + r2);
    outP[base0]     = v;
    outQ[base0 + 1] = v;
}

extern "C" void kernel_launch(void* const* d_in, const int* in_sizes, int n_in,
                              void* d_out, int out_size)
{
    (void)in_sizes; (void)n_in; (void)out_size;
    const float4* vel = (const float4*)d_in[0];
    float*        out = (float*)d_out;

    uint2 *AP = nullptr, *AQ = nullptr, *BP = nullptr;
    cudaGetSymbolAddress((void**)&AP, g_AP);
    cudaGetSymbolAddress((void**)&AQ, g_AQ);
    cudaGetSymbolAddress((void**)&BP, g_BP);

    vecint_convert<<<NVOX / 4 / 256, 256>>>(vel, AP, AQ);

    const dim3 blk(32, 4, 2);
    const dim3 grd(DIMS / 32, DIMS / 4, (DIMS / 2) * NB);

    vecint_step_pair<false><<<grd, blk>>>(AP, AQ, nullptr, BP);   // 1: A->B
    vecint_step_plain      <<<grd, blk>>>(BP, AP, AQ);            // 2: B->A
    vecint_step_pair<false><<<grd, blk>>>(AP, AQ, nullptr, BP);   // 3: A->B
    vecint_step_plain      <<<grd, blk>>>(BP, AP, AQ);            // 4: B->A
    vecint_step_pair<false><<<grd, blk>>>(AP, AQ, nullptr, BP);   // 5: A->B
    vecint_step_plain      <<<grd, blk>>>(BP, AP, AQ);            // 6: B->A
    vecint_step_pair<true ><<<grd, blk>>>(AP, AQ, out, nullptr);  // 7: A->out
}

// round 6
// speedup vs baseline: 1.1229x; 1.0422x over previous
#include <cuda_runtime.h>
#include <cuda_fp16.h>

// VecInt: 7-step scaling-and-squaring integration of [2,128,128,128,3] f32.
//   v0 = vel/128;  v <- v + trilinear_warp(v, v)  x7
//
// R6: fp16x4 storage, single copy per ping-pong buffer (67MB total live set —
// the L2-friendly regime proven by R2). Per trilinear (d,h)-row, the two
// w-corners are fetched with ONE 16B-aligned LDG.128 at (row & ~1):
//   iw0 even -> chunk {iw0, iw0+1} covers both corners;
//   iw0 odd  -> chunk {iw0-1, iw0} gives the lower corner, plus one
//               predicated LDG.64 for the upper corner.
// This cuts L1 wavefronts ~30% (the measured bottleneck) with no extra
// footprint. All math in f32; results bit-identical to R2.

static constexpr int DIMS = 128;
static constexpr int NB   = 2;
static constexpr int NVOX = NB * DIMS * DIMS * DIMS;

__device__ __align__(16) uint2 g_bufA[NVOX + 2];
__device__ __align__(16) uint2 g_bufB[NVOX + 2];

__device__ __forceinline__ void h4_to_f3(uint2 u, float& x, float& y, float& z)
{
    __half2 h01 = *reinterpret_cast<__half2*>(&u.x);
    __half2 h23 = *reinterpret_cast<__half2*>(&u.y);
    float2  f01 = __half22float2(h01);
    x = f01.x; y = f01.y; z = __low2float(h23);
}

__device__ __forceinline__ uint2 f3_to_h4(float x, float y, float z)
{
    __half2 h01 = __floats2half2_rn(x, y);
    __half2 h23 = __floats2half2_rn(z, 0.0f);
    uint2 u;
    u.x = *reinterpret_cast<unsigned int*>(&h01);
    u.y = *reinterpret_cast<unsigned int*>(&h23);
    return u;
}

// ---------- pass 0: packed f32x3 -> fp16x4, folding 1/128 -------------------
__global__ __launch_bounds__(256)
void vecint_convert(const float4* __restrict__ in, uint4* __restrict__ out)
{
    const int t = blockIdx.x * blockDim.x + threadIdx.x;   // voxel-quad id
    const float s = 1.0f / 128.0f;
    const float4 a = in[3 * t + 0];
    const float4 b = in[3 * t + 1];
    const float4 c = in[3 * t + 2];
    const uint2 v0 = f3_to_h4(a.x * s, a.y * s, a.z * s);
    const uint2 v1 = f3_to_h4(a.w * s, b.x * s, b.y * s);
    const uint2 v2 = f3_to_h4(b.z * s, b.w * s, c.x * s);
    const uint2 v3 = f3_to_h4(c.y * s, c.z * s, c.w * s);
    out[2 * t + 0] = make_uint4(v0.x, v0.y, v1.x, v1.y);
    out[2 * t + 1] = make_uint4(v2.x, v2.y, v3.x, v3.y);
}

// ---------- integration step ------------------------------------------------
template<bool OUT_PACKED>
__global__ __launch_bounds__(256)
void vecint_step(const uint2* __restrict__ in_v,
                 float*       __restrict__ out_p,   // packed f32 (last pass)
                 uint2*       __restrict__ out_v)
{
    const int w  = blockIdx.x * 32 + threadIdx.x;
    const int h  = blockIdx.y * 4  + threadIdx.y;
    const int zb = blockIdx.z;
    const int b  = zb >> 6;
    const int d  = ((zb & 63) << 1) + threadIdx.z;

    const int base = ((b * DIMS + d) * DIMS + h) * DIMS + w;

    float f0, f1, f2;
    h4_to_f3(in_v[base], f0, f1, f2);

    const float ld = fminf(fmaxf((float)d + f0, 0.0f), 127.0f);
    const float lh = fminf(fmaxf((float)h + f1, 0.0f), 127.0f);
    const float lw = fminf(fmaxf((float)w + f2, 0.0f), 127.0f);

    const float fd = floorf(ld), fh = floorf(lh), fw = floorf(lw);
    const int   id0 = (int)fd,  ih0 = (int)fh,  iw0 = (int)fw;
    const float wd1 = ld - fd,  wh1 = lh - fh,  ww1 = lw - fw;
    const float wd0 = 1.0f - wd1, wh0 = 1.0f - wh1, ww0 = 1.0f - ww1;

    // Row offsets (fold the border clamp into 0-or-stride deltas).
    const int dd  = (id0 < 127) ? (DIMS * DIMS) : 0;
    const int dh  = (ih0 < 127) ? DIMS : 0;
    const int r00 = ((b * DIMS + id0) * DIMS + ih0) * DIMS + iw0;
    const int r01 = r00 + dh;
    const int r10 = r00 + dd;
    const int r11 = r10 + dh;

    const bool odd = (iw0 & 1) != 0;

    float r0 = 0.0f, r1 = 0.0f, r2 = 0.0f;
#pragma unroll
    for (int k = 0; k < 4; ++k) {
        const int   row = (k == 0) ? r00 : (k == 1) ? r01 : (k == 2) ? r10 : r11;
        const float wdh = ((k & 2) ? wd1 : wd0) * ((k & 1) ? wh1 : wh0);
        const float wg0 = wdh * ww0;
        const float wg1 = wdh * ww1;   // ww1==0 whenever row+1 would stray

        // Aligned 16B chunk covering {row&~1, (row&~1)+1}.
        const uint4 ck = *reinterpret_cast<const uint4*>(in_v + (row & ~1));
        uint2 ex = make_uint2(0u, 0u);
        if (odd) ex = __ldg(in_v + row + 1);          // predicated LDG.64

        const uint2 lo = make_uint2(ck.x, ck.y);
        const uint2 hi = make_uint2(ck.z, ck.w);
        const uint2 v0 = odd ? hi : lo;               // corner iw0
        const uint2 v1 = odd ? ex : hi;               // corner iw0+1

        float x0, y0, z0, x1, y1, z1;
        h4_to_f3(v0, x0, y0, z0);
        h4_to_f3(v1, x1, y1, z1);
        r0 = fmaf(wg0, x0, fmaf(wg1, x1, r0));
        r1 = fmaf(wg0, y0, fmaf(wg1, y1, r1));
        r2 = fmaf(wg0, z0, fmaf(wg1, z1, r2));
    }

    const float o0 = f0 + r0, o1 = f1 + r1, o2 = f2 + r2;
    if (OUT_PACKED) {
        float* p = out_p + (size_t)base * 3;
        p[0] = o0; p[1] = o1; p[2] = o2;
    } else {
        out_v[base] = f3_to_h4(o0, o1, o2);
    }
}

extern "C" void kernel_launch(void* const* d_in, const int* in_sizes, int n_in,
                              void* d_out, int out_size)
{
    (void)in_sizes; (void)n_in; (void)out_size;
    const float4* vel = (const float4*)d_in[0];
    float*        out = (float*)d_out;

    uint2 *A = nullptr, *B = nullptr;
    cudaGetSymbolAddress((void**)&A, g_bufA);
    cudaGetSymbolAddress((void**)&B, g_bufB);

    vecint_convert<<<NVOX / 4 / 256, 256>>>(vel, (uint4*)A);

    const dim3 blk(32, 4, 2);
    const dim3 grd(DIMS / 32, DIMS / 4, (DIMS / 2) * NB);

    vecint_step<false><<<grd, blk>>>(A, nullptr, B);   // 1
    vecint_step<false><<<grd, blk>>>(B, nullptr, A);   // 2
    vecint_step<false><<<grd, blk>>>(A, nullptr, B);   // 3
    vecint_step<false><<<grd, blk>>>(B, nullptr, A);   // 4
    vecint_step<false><<<grd, blk>>>(A, nullptr, B);   // 5
    vecint_step<false><<<grd, blk>>>(B, nullptr, A);   // 6
    vecint_step<true ><<<grd, blk>>>(A, out, nullptr); // 7
}

// round 7
// speedup vs baseline: 1.4136x; 1.2590x over previous
#include <cuda_runtime.h>
#include <cuda_fp16.h>

// VecInt: 7-step scaling-and-squaring integration of [2,128,128,128,3] f32.
//   v0 = vel/128;  v <- v + trilinear_warp(v, v)  x7
//
// R7: back to the R2 memory structure (fp16x4 voxels, single copy per
// ping-pong buffer, 8x LDG.64 gather — the measured L1-wavefront optimum),
// with the issue/latency side tightened:
//   - all 8 corner loads batched up-front (MLP ~9, one scoreboard drain)
//   - strength-reduced row addressing (0-or-stride border deltas, no min/IMAD
//     chains)
// Arithmetic order identical to R5/R6 (measured rel_err 4.6838e-4).

static constexpr int DIMS = 128;
static constexpr int NB   = 2;
static constexpr int NVOX = NB * DIMS * DIMS * DIMS;

// +2 pad slots: the zero-weighted stray read at iw0==127 lands here.
// __device__ globals are zero-initialized, and fp16 zero bits decode to 0.0.
__device__ __align__(16) uint2 g_bufA[NVOX + 2];
__device__ __align__(16) uint2 g_bufB[NVOX + 2];

__device__ __forceinline__ void h4_to_f3(uint2 u, float& x, float& y, float& z)
{
    __half2 h01 = *reinterpret_cast<__half2*>(&u.x);
    __half2 h23 = *reinterpret_cast<__half2*>(&u.y);
    float2  f01 = __half22float2(h01);
    x = f01.x; y = f01.y; z = __low2float(h23);
}

__device__ __forceinline__ uint2 f3_to_h4(float x, float y, float z)
{
    __half2 h01 = __floats2half2_rn(x, y);
    __half2 h23 = __floats2half2_rn(z, 0.0f);
    uint2 u;
    u.x = *reinterpret_cast<unsigned int*>(&h01);
    u.y = *reinterpret_cast<unsigned int*>(&h23);
    return u;
}

// ---------- pass 0: packed f32x3 -> fp16x4, folding 1/128 -------------------
__global__ __launch_bounds__(256)
void vecint_convert(const float4* __restrict__ in, uint4* __restrict__ out)
{
    const int t = blockIdx.x * blockDim.x + threadIdx.x;   // voxel-quad id
    const float s = 1.0f / 128.0f;
    const float4 a = in[3 * t + 0];
    const float4 b = in[3 * t + 1];
    const float4 c = in[3 * t + 2];
    const uint2 v0 = f3_to_h4(a.x * s, a.y * s, a.z * s);
    const uint2 v1 = f3_to_h4(a.w * s, b.x * s, b.y * s);
    const uint2 v2 = f3_to_h4(b.z * s, b.w * s, c.x * s);
    const uint2 v3 = f3_to_h4(c.y * s, c.z * s, c.w * s);
    out[2 * t + 0] = make_uint4(v0.x, v0.y, v1.x, v1.y);
    out[2 * t + 1] = make_uint4(v2.x, v2.y, v3.x, v3.y);
}

// ---------- integration step ------------------------------------------------
template<bool OUT_PACKED>
__global__ __launch_bounds__(256)
void vecint_step(const uint2* __restrict__ in_v,
                 float*       __restrict__ out_p,   // packed f32 (last pass)
                 uint2*       __restrict__ out_v)
{
    const int w  = blockIdx.x * 32 + threadIdx.x;
    const int h  = blockIdx.y * 4  + threadIdx.y;
    const int zb = blockIdx.z;
    const int b  = zb >> 6;
    const int d  = ((zb & 63) << 1) + threadIdx.z;

    const int base = ((b * DIMS + d) * DIMS + h) * DIMS + w;

    float f0, f1, f2;
    h4_to_f3(in_v[base], f0, f1, f2);

    const float ld = fminf(fmaxf((float)d + f0, 0.0f), 127.0f);
    const float lh = fminf(fmaxf((float)h + f1, 0.0f), 127.0f);
    const float lw = fminf(fmaxf((float)w + f2, 0.0f), 127.0f);

    const float fd = floorf(ld), fh = floorf(lh), fw = floorf(lw);
    const int   id0 = (int)fd,  ih0 = (int)fh,  iw0 = (int)fw;
    const float wd1 = ld - fd,  wh1 = lh - fh,  ww1 = lw - fw;
    const float wd0 = 1.0f - wd1, wh0 = 1.0f - wh1, ww0 = 1.0f - ww1;

    // Border clamp folded into 0-or-stride deltas (bit-exact vs min()).
    const int dd  = (id0 < 127) ? (DIMS * DIMS) : 0;
    const int dh  = (ih0 < 127) ? DIMS : 0;
    const int r00 = ((b * DIMS + id0) * DIMS + ih0) * DIMS + iw0;
    const int r01 = r00 + dh;
    const int r10 = r00 + dd;
    const int r11 = r10 + dh;

    // Front-loaded gather burst: 8 independent LDG.64 in flight at once.
    // (row+1 at iw0==127 is zero-weighted (ww1==0) and in-bounds via pad.)
    const uint2 u00a = in_v[r00];     const uint2 u00b = in_v[r00 + 1];
    const uint2 u01a = in_v[r01];     const uint2 u01b = in_v[r01 + 1];
    const uint2 u10a = in_v[r10];     const uint2 u10b = in_v[r10 + 1];
    const uint2 u11a = in_v[r11];     const uint2 u11b = in_v[r11 + 1];

    // (d,h) blend weights.
    const float w00 = wd0 * wh0, w01 = wd0 * wh1;
    const float w10 = wd1 * wh0, w11 = wd1 * wh1;

    float r0 = 0.0f, r1 = 0.0f, r2 = 0.0f;
    float x0, y0, z0, x1, y1, z1;

    h4_to_f3(u00a, x0, y0, z0);  h4_to_f3(u00b, x1, y1, z1);
    {   const float g0 = w00 * ww0, g1 = w00 * ww1;
        r0 = fmaf(g0, x0, fmaf(g1, x1, r0));
        r1 = fmaf(g0, y0, fmaf(g1, y1, r1));
        r2 = fmaf(g0, z0, fmaf(g1, z1, r2)); }

    h4_to_f3(u01a, x0, y0, z0);  h4_to_f3(u01b, x1, y1, z1);
    {   const float g0 = w01 * ww0, g1 = w01 * ww1;
        r0 = fmaf(g0, x0, fmaf(g1, x1, r0));
        r1 = fmaf(g0, y0, fmaf(g1, y1, r1));
        r2 = fmaf(g0, z0, fmaf(g1, z1, r2)); }

    h4_to_f3(u10a, x0, y0, z0);  h4_to_f3(u10b, x1, y1, z1);
    {   const float g0 = w10 * ww0, g1 = w10 * ww1;
        r0 = fmaf(g0, x0, fmaf(g1, x1, r0));
        r1 = fmaf(g0, y0, fmaf(g1, y1, r1));
        r2 = fmaf(g0, z0, fmaf(g1, z1, r2)); }

    h4_to_f3(u11a, x0, y0, z0);  h4_to_f3(u11b, x1, y1, z1);
    {   const float g0 = w11 * ww0, g1 = w11 * ww1;
        r0 = fmaf(g0, x0, fmaf(g1, x1, r0));
        r1 = fmaf(g0, y0, fmaf(g1, y1, r1));
        r2 = fmaf(g0, z0, fmaf(g1, z1, r2)); }

    const float o0 = f0 + r0, o1 = f1 + r1, o2 = f2 + r2;
    if (OUT_PACKED) {
        float* p = out_p + (size_t)base * 3;
        p[0] = o0; p[1] = o1; p[2] = o2;
    } else {
        out_v[base] = f3_to_h4(o0, o1, o2);
    }
}

extern "C" void kernel_launch(void* const* d_in, const int* in_sizes, int n_in,
                              void* d_out, int out_size)
{
    (void)in_sizes; (void)n_in; (void)out_size;
    const float4* vel = (const float4*)d_in[0];
    float*        out = (float*)d_out;

    uint2 *A = nullptr, *B = nullptr;
    cudaGetSymbolAddress((void**)&A, g_bufA);
    cudaGetSymbolAddress((void**)&B, g_bufB);

    vecint_convert<<<NVOX / 4 / 256, 256>>>(vel, (uint4*)A);

    const dim3 blk(32, 4, 2);
    const dim3 grd(DIMS / 32, DIMS / 4, (DIMS / 2) * NB);

    vecint_step<false><<<grd, blk>>>(A, nullptr, B);   // 1
    vecint_step<false><<<grd, blk>>>(B, nullptr, A);   // 2
    vecint_step<false><<<grd, blk>>>(A, nullptr, B);   // 3
    vecint_step<false><<<grd, blk>>>(B, nullptr, A);   // 4
    vecint_step<false><<<grd, blk>>>(A, nullptr, B);   // 5
    vecint_step<false><<<grd, blk>>>(B, nullptr, A);   // 6
    vecint_step<true ><<<grd, blk>>>(A, out, nullptr); // 7
}

// round 8
// speedup vs baseline: 1.5411x; 1.0902x over previous
#include <cuda_runtime.h>
#include <cuda_fp16.h>

// VecInt: 7-step scaling-and-squaring integration of [2,128,128,128,3] f32.
//   v0 = vel/128;  v <- v + trilinear_warp(v, v)  x7
//
// R8 = R7 (fp16x4 voxels, single-copy ping-pong, 8x LDG.64 front-loaded
// gather — the measured L1-wavefront optimum) + 2 voxels per thread
// (d and d+2) with both gather bursts issued back-to-back: ~18 loads in
// flight per thread to hide the L2 return latency that accounted for the
// ~6.6us/pass gap between the measured pass time and its L1-wavefront floor.
// Arithmetic identical to R7 (rel_err 4.6838e-4).

static constexpr int DIMS = 128;
static constexpr int NB   = 2;
static constexpr int NVOX = NB * DIMS * DIMS * DIMS;

// +2 pad: zero-weighted stray read at iw0==127 lands here (zero-init'd).
__device__ __align__(16) uint2 g_bufA[NVOX + 2];
__device__ __align__(16) uint2 g_bufB[NVOX + 2];

__device__ __forceinline__ void h4_to_f3(uint2 u, float& x, float& y, float& z)
{
    __half2 h01 = *reinterpret_cast<__half2*>(&u.x);
    __half2 h23 = *reinterpret_cast<__half2*>(&u.y);
    float2  f01 = __half22float2(h01);
    x = f01.x; y = f01.y; z = __low2float(h23);
}

__device__ __forceinline__ uint2 f3_to_h4(float x, float y, float z)
{
    __half2 h01 = __floats2half2_rn(x, y);
    __half2 h23 = __floats2half2_rn(z, 0.0f);
    uint2 u;
    u.x = *reinterpret_cast<unsigned int*>(&h01);
    u.y = *reinterpret_cast<unsigned int*>(&h23);
    return u;
}

// ---------- pass 0: packed f32x3 -> fp16x4, folding 1/128 -------------------
__global__ __launch_bounds__(256)
void vecint_convert(const float4* __restrict__ in, uint4* __restrict__ out)
{
    const int t = blockIdx.x * blockDim.x + threadIdx.x;
    const float s = 1.0f / 128.0f;
    const float4 a = in[3 * t + 0];
    const float4 b = in[3 * t + 1];
    const float4 c = in[3 * t + 2];
    const uint2 v0 = f3_to_h4(a.x * s, a.y * s, a.z * s);
    const uint2 v1 = f3_to_h4(a.w * s, b.x * s, b.y * s);
    const uint2 v2 = f3_to_h4(b.z * s, b.w * s, c.x * s);
    const uint2 v3 = f3_to_h4(c.y * s, c.z * s, c.w * s);
    out[2 * t + 0] = make_uint4(v0.x, v0.y, v1.x, v1.y);
    out[2 * t + 1] = make_uint4(v2.x, v2.y, v3.x, v3.y);
}

// ---------- per-voxel coordinate state --------------------------------------
struct Vx {
    int   r00, r01, r10, r11, base;
    float f0, f1, f2, w00, w01, w10, w11, ww0, ww1;
};

__device__ __forceinline__ Vx vx_setup(const uint2* __restrict__ in_v,
                                       int b, int d, int h, int w)
{
    Vx v;
    v.base = ((b * DIMS + d) * DIMS + h) * DIMS + w;
    h4_to_f3(in_v[v.base], v.f0, v.f1, v.f2);

    const float ldc = fminf(fmaxf((float)d + v.f0, 0.0f), 127.0f);
    const float lhc = fminf(fmaxf((float)h + v.f1, 0.0f), 127.0f);
    const float lwc = fminf(fmaxf((float)w + v.f2, 0.0f), 127.0f);

    const float fd = floorf(ldc), fh = floorf(lhc), fw = floorf(lwc);
    const int   id0 = (int)fd,  ih0 = (int)fh,  iw0 = (int)fw;
    const float wd1 = ldc - fd, wh1 = lhc - fh;
    const float wd0 = 1.0f - wd1, wh0 = 1.0f - wh1;
    v.ww1 = lwc - fw; v.ww0 = 1.0f - v.ww1;

    const int dd = (id0 < 127) ? (DIMS * DIMS) : 0;
    const int dh = (ih0 < 127) ? DIMS : 0;
    v.r00 = ((b * DIMS + id0) * DIMS + ih0) * DIMS + iw0;
    v.r01 = v.r00 + dh;
    v.r10 = v.r00 + dd;
    v.r11 = v.r10 + dh;

    v.w00 = wd0 * wh0; v.w01 = wd0 * wh1;
    v.w10 = wd1 * wh0; v.w11 = wd1 * wh1;
    return v;
}

struct Gather { uint2 a0, b0, a1, b1, a2, b2, a3, b3; };

__device__ __forceinline__ Gather vx_load(const uint2* __restrict__ in_v,
                                          const Vx& v)
{
    Gather g;
    g.a0 = in_v[v.r00]; g.b0 = in_v[v.r00 + 1];
    g.a1 = in_v[v.r01]; g.b1 = in_v[v.r01 + 1];
    g.a2 = in_v[v.r10]; g.b2 = in_v[v.r10 + 1];
    g.a3 = in_v[v.r11]; g.b3 = in_v[v.r11 + 1];
    return g;
}

__device__ __forceinline__ void vx_blend(const Vx& v, const Gather& g,
                                         float& o0, float& o1, float& o2)
{
    float r0 = 0.0f, r1 = 0.0f, r2 = 0.0f;
    float x0, y0, z0, x1, y1, z1;
#define BLEND(A, B, WDH)                                                  \
    h4_to_f3(A, x0, y0, z0); h4_to_f3(B, x1, y1, z1);                     \
    {   const float g0 = (WDH) * v.ww0, g1 = (WDH) * v.ww1;               \
        r0 = fmaf(g0, x0, fmaf(g1, x1, r0));                              \
        r1 = fmaf(g0, y0, fmaf(g1, y1, r1));                              \
        r2 = fmaf(g0, z0, fmaf(g1, z1, r2)); }
    BLEND(g.a0, g.b0, v.w00)
    BLEND(g.a1, g.b1, v.w01)
    BLEND(g.a2, g.b2, v.w10)
    BLEND(g.a3, g.b3, v.w11)
#undef BLEND
    o0 = v.f0 + r0; o1 = v.f1 + r1; o2 = v.f2 + r2;
}

// ---------- integration step: 2 voxels (d, d+2) per thread ------------------
template<bool OUT_PACKED>
__global__ __launch_bounds__(256)
void vecint_step(const uint2* __restrict__ in_v,
                 float*       __restrict__ out_p,
                 uint2*       __restrict__ out_v)
{
    const int w  = blockIdx.x * 32 + threadIdx.x;
    const int h  = blockIdx.y * 4  + threadIdx.y;
    const int zb = blockIdx.z;                  // 64: 32 d-quads x 2 batches
    const int b  = zb >> 5;
    const int d  = ((zb & 31) << 2) + threadIdx.z;   // d and d+2 per thread

    // Setup + front-loaded gather bursts for both voxels (~18 loads in flight)
    const Vx vA = vx_setup(in_v, b, d,     h, w);
    const Vx vB = vx_setup(in_v, b, d + 2, h, w);
    const Gather gA = vx_load(in_v, vA);
    const Gather gB = vx_load(in_v, vB);

    float a0, a1, a2, b0, b1, b2;
    vx_blend(vA, gA, a0, a1, a2);
    vx_blend(vB, gB, b0, b1, b2);

    if (OUT_PACKED) {
        float* pA = out_p + (size_t)vA.base * 3;
        pA[0] = a0; pA[1] = a1; pA[2] = a2;
        float* pB = out_p + (size_t)vB.base * 3;
        pB[0] = b0; pB[1] = b1; pB[2] = b2;
    } else {
        out_v[vA.base] = f3_to_h4(a0, a1, a2);
        out_v[vB.base] = f3_to_h4(b0, b1, b2);
    }
}

extern "C" void kernel_launch(void* const* d_in, const int* in_sizes, int n_in,
                              void* d_out, int out_size)
{
    (void)in_sizes; (void)n_in; (void)out_size;
    const float4* vel = (const float4*)d_in[0];
    float*        out = (float*)d_out;

    uint2 *A = nullptr, *B = nullptr;
    cudaGetSymbolAddress((void**)&A, g_bufA);
    cudaGetSymbolAddress((void**)&B, g_bufB);

    vecint_convert<<<NVOX / 4 / 256, 256>>>(vel, (uint4*)A);

    const dim3 blk(32, 4, 2);
    const dim3 grd(DIMS / 32, DIMS / 4, (DIMS / 4) * NB);   // 2 voxels/thread

    vecint_step<false><<<grd, blk>>>(A, nullptr, B);   // 1
    vecint_step<false><<<grd, blk>>>(B, nullptr, A);   // 2
    vecint_step<false><<<grd, blk>>>(A, nullptr, B);   // 3
    vecint_step<false><<<grd, blk>>>(B, nullptr, A);   // 4
    vecint_step<false><<<grd, blk>>>(A, nullptr, B);   // 5
    vecint_step<false><<<grd, blk>>>(B, nullptr, A);   // 6
    vecint_step<true ><<<grd, blk>>>(A, out, nullptr); // 7
}